// round 16
// baseline (speedup 1.0000x reference)
#include <cuda_runtime.h>
#include <cstdint>

#define NB   32
#define NCH  3
#define HH   128
#define RR   127
#define NLOC (NB*RR*RR)
#define TPB  128
#define ROWB 48            // staging row pitch (conflict-free: 12r mod 32 banks distinct)

struct SmemT {
    float U[256];                                        // circuit matrix, f32
    __align__(16) unsigned char stage[4][2][2][32 * ROWB];  // [warp][buf][hi/lo][row]
};

__device__ __forceinline__ uint32_t smem_u32(const void* p) {
    uint32_t a;
    asm("{ .reg .u64 t; cvta.to.shared.u64 t, %1; cvt.u32.u64 %0, t; }" : "=r"(a) : "l"(p));
    return a;
}
// bf16x2 truncation-pack via single PRMT: low half = hi16(a), high = hi16(b)
__device__ __forceinline__ uint32_t pk_hi(float a, float b) {
    uint32_t d;
    asm("prmt.b32 %0, %1, %2, 0x7632;" : "=r"(d) : "r"(__float_as_uint(a)), "r"(__float_as_uint(b)));
    return d;
}
__device__ __forceinline__ float hi_f32(float a) {
    return __uint_as_float(__float_as_uint(a) & 0xFFFF0000u);
}
__device__ __forceinline__ void ldsm4(uint32_t& r0, uint32_t& r1, uint32_t& r2, uint32_t& r3,
                                      uint32_t addr) {
    asm volatile("ldmatrix.sync.aligned.m8n8.x4.shared.b16 {%0,%1,%2,%3}, [%4];"
                 : "=r"(r0), "=r"(r1), "=r"(r2), "=r"(r3) : "r"(addr) : "memory");
}
__device__ __forceinline__ void mma16816(float& d0, float& d1, float& d2, float& d3,
                                         uint32_t a0, uint32_t a1, uint32_t a2, uint32_t a3,
                                         uint32_t b0, uint32_t b1) {
    asm volatile("mma.sync.aligned.m16n8k16.row.col.f32.bf16.bf16.f32 "
                 "{%0,%1,%2,%3}, {%4,%5,%6,%7}, {%8,%9}, {%0,%1,%2,%3};"
                 : "+f"(d0), "+f"(d1), "+f"(d2), "+f"(d3)
                 : "r"(a0), "r"(a1), "r"(a2), "r"(a3), "r"(b0), "r"(b1));
}

__global__ void rqcnn_mma(const float* __restrict__ x,
                          const float* __restrict__ w,
                          float* __restrict__ out) {
    __shared__ SmemT sm;
    int tid  = threadIdx.x;
    int wid  = tid >> 5;
    int lane = tid & 31;

    // ---- build U (threads 0-15, column each) ----
    if (tid < 16) {
        int jj = tid;
        float m[16];
#pragma unroll
        for (int i = 0; i < 16; i++) m[i] = (i == jj) ? 1.0f : 0.0f;
        for (int layer = 0; layer < 4; layer++) {
#pragma unroll
            for (int q = 0; q < 4; q++) {
                float t = 0.5f * w[layer * 4 + q];
                float c, s;
                __sincosf(t, &s, &c);
                int mask = 8 >> q;
#pragma unroll
                for (int i0 = 0; i0 < 16; i0++) {
                    if (i0 & mask) continue;
                    int i1 = i0 | mask;
                    float a0 = m[i0], a1 = m[i1];
                    m[i0] = c * a0 - s * a1;
                    m[i1] = s * a0 + c * a1;
                }
            }
#pragma unroll
            for (int i = 0; i < 16; i++)
                if ((i & 8) && !(i & 4)) { float tt = m[i]; m[i] = m[i | 4]; m[i | 4] = tt; }
#pragma unroll
            for (int i = 0; i < 16; i++)
                if ((i & 2) && !(i & 1)) { float tt = m[i]; m[i] = m[i | 1]; m[i | 1] = tt; }
#pragma unroll
            for (int i = 0; i < 16; i++)
                if ((i & 4) && !(i & 2)) { float tt = m[i]; m[i] = m[i | 2]; m[i | 2] = tt; }
        }
#pragma unroll
        for (int i = 0; i < 16; i++) sm.U[i * 16 + jj] = m[i];
    }
    __syncthreads();

    int t = lane & 3, g = lane >> 2;

    // ---- B fragments (built once): B[k][n] = U[n][k], n = g + 8*nt ----
    uint32_t bh0[2], bh1[2], bl0[2], bl1[2];
#pragma unroll
    for (int nt = 0; nt < 2; nt++) {
        const float* Ur = sm.U + (g + 8 * nt) * 16;
        float u0 = Ur[2 * t],     u1 = Ur[2 * t + 1];
        float u2 = Ur[2 * t + 8], u3 = Ur[2 * t + 9];
        bh0[nt] = pk_hi(u0, u1);
        bh1[nt] = pk_hi(u2, u3);
        bl0[nt] = pk_hi(u0 - hi_f32(u0), u1 - hi_f32(u1));
        bl1[nt] = pk_hi(u2 - hi_f32(u2), u3 - hi_f32(u3));
    }

    // ---- per-lane patch ----
    int gid = blockIdx.x * TPB + tid;
    int gcl = (gid < NLOC) ? gid : (NLOC - 1);
    int j   = gcl % RR;
    int t2  = gcl / RR;
    int i   = t2 % RR;
    int b   = t2 / RR;
    const float HPI = 1.57079632679489662f;

    // double-buffered staging bases
    uint32_t hib0 = smem_u32(&sm.stage[wid][0][0][0]);
    uint32_t lob0 = smem_u32(&sm.stage[wid][0][1][0]);
    uint32_t hib1 = smem_u32(&sm.stage[wid][1][0][0]);
    uint32_t lob1 = smem_u32(&sm.stage[wid][1][1][0]);
    uint32_t lmoff = (uint32_t)((lane & 15) * ROWB + (lane & 16));
    uint32_t rowoff = (uint32_t)(lane * ROWB);

    float P[2][2][4];
#pragma unroll
    for (int a = 0; a < 2; a++)
#pragma unroll
        for (int n = 0; n < 2; n++)
#pragma unroll
            for (int e = 0; e < 4; e++) P[a][n][e] = 0.0f;

    const float* px = x + (((b * NCH) * HH) + i) * HH + j;

    // prefetch channel 0 pixels
    float q00 = px[0], q01 = px[1], q10 = px[HH], q11 = px[HH + 1];
    px += HH * HH;

#pragma unroll 1
    for (int c = 0; c < NCH; c++) {
        float p00 = q00, p01 = q01, p10 = q10, p11 = q11;
        if (c < NCH - 1) {       // prefetch next channel before compute/MMA
            q00 = px[0]; q01 = px[1]; q10 = px[HH]; q11 = px[HH + 1];
            px += HH * HH;
        }

        uint32_t sel = (uint32_t)(c & 1);
        uint32_t hb = sel ? hib1 : hib0;
        uint32_t lb = sel ? lob1 : lob0;

        // buffer 0 is reused at c==2: must wait for c==0's ldmatrix across lanes
        if (c == 2) __syncwarp();

        float ca, sa, cb, sb, cc, sc, cd, sd;
        __sincosf(p00 * HPI, &sa, &ca);
        __sincosf(p01 * HPI, &sb, &cb);
        __sincosf(p10 * HPI, &sc, &cc);
        __sincosf(p11 * HPI, &sd, &cd);
        float ab00 = ca * cb, ab01 = ca * sb, ab10 = sa * cb, ab11 = sa * sb;
        float cd00 = cc * cd, cd01 = cc * sd, cd10 = sc * cd, cd11 = sc * sd;
        float s[16];
        s[0]  = ab00 * cd00; s[1]  = ab00 * cd01; s[2]  = ab00 * cd10; s[3]  = ab00 * cd11;
        s[4]  = ab01 * cd00; s[5]  = ab01 * cd01; s[6]  = ab01 * cd10; s[7]  = ab01 * cd11;
        s[8]  = ab10 * cd00; s[9]  = ab10 * cd01; s[10] = ab10 * cd10; s[11] = ab10 * cd11;
        s[12] = ab11 * cd00; s[13] = ab11 * cd01; s[14] = ab11 * cd10; s[15] = ab11 * cd11;

        // split to bf16 hi + lo (truncation-packed via PRMT), stage row=lane
        uint32_t hp[8], lp[8];
#pragma unroll
        for (int p = 0; p < 8; p++) {
            float f0 = s[2 * p], f1 = s[2 * p + 1];
            hp[p] = pk_hi(f0, f1);
            lp[p] = pk_hi(f0 - hi_f32(f0), f1 - hi_f32(f1));
        }
        uint4* hrow = reinterpret_cast<uint4*>(
            reinterpret_cast<unsigned char*>(sm.stage) + (hb - smem_u32(sm.stage)) + rowoff);
        uint4* lrow = reinterpret_cast<uint4*>(
            reinterpret_cast<unsigned char*>(sm.stage) + (lb - smem_u32(sm.stage)) + rowoff);
        hrow[0] = make_uint4(hp[0], hp[1], hp[2], hp[3]);
        hrow[1] = make_uint4(hp[4], hp[5], hp[6], hp[7]);
        lrow[0] = make_uint4(lp[0], lp[1], lp[2], lp[3]);
        lrow[1] = make_uint4(lp[4], lp[5], lp[6], lp[7]);
        __syncwarp();   // staging visible to all lanes before collective ldmatrix

#pragma unroll
        for (int mt = 0; mt < 2; mt++) {
            uint32_t ah0, ah1, ah2, ah3, al0, al1, al2, al3;
            ldsm4(ah0, ah1, ah2, ah3, hb + mt * (16 * ROWB) + lmoff);
            ldsm4(al0, al1, al2, al3, lb + mt * (16 * ROWB) + lmoff);
#pragma unroll
            for (int nt = 0; nt < 2; nt++) {
                float d0 = 0.f, d1 = 0.f, d2 = 0.f, d3 = 0.f;
                mma16816(d0, d1, d2, d3, ah0, ah1, ah2, ah3, bh0[nt], bh1[nt]);
                mma16816(d0, d1, d2, d3, al0, al1, al2, al3, bh0[nt], bh1[nt]);
                mma16816(d0, d1, d2, d3, ah0, ah1, ah2, ah3, bl0[nt], bl1[nt]);
                // lo x lo term dropped: ~2^-34 relative, numerically invisible
                P[mt][nt][0] = fmaf(d0, d0, P[mt][nt][0]);
                P[mt][nt][1] = fmaf(d1, d1, P[mt][nt][1]);
                P[mt][nt][2] = fmaf(d2, d2, P[mt][nt][2]);
                P[mt][nt][3] = fmaf(d3, d3, P[mt][nt][3]);
            }
        }
    }

    // ---- epilogue: per-lane combos + shfl butterflies (signs folded in order) ----
    float zq[4][4];   // [mslot][q]
#pragma unroll
    for (int mt = 0; mt < 2; mt++) {
#pragma unroll
        for (int rs = 0; rs < 2; rs++) {
            float Pa = P[mt][0][rs * 2 + 0];   // col 2t
            float Pb = P[mt][0][rs * 2 + 1];   // col 2t+1
            float Pc = P[mt][1][rs * 2 + 0];   // col 2t+8
            float Pd = P[mt][1][rs * 2 + 1];   // col 2t+9
            float ta = Pa + Pb, tb = Pc + Pd;
            float T  = ta + tb;
            int ms = mt * 2 + rs;
            // z0: plain reduce of (ta - tb); z3: plain reduce of alt-diff
            float c0 = ta - tb;
            c0 += __shfl_xor_sync(0xffffffffu, c0, 1);
            c0 += __shfl_xor_sync(0xffffffffu, c0, 2);
            zq[ms][0] = c0;
            float c3 = (Pa - Pb) + (Pc - Pd);
            c3 += __shfl_xor_sync(0xffffffffu, c3, 1);
            c3 += __shfl_xor_sync(0xffffffffu, c3, 2);
            zq[ms][3] = c3;
            // z1 = (T0+T1)-(T2+T3): xor1 add, xor2 sub
            float u = T + __shfl_xor_sync(0xffffffffu, T, 1);
            zq[ms][1] = u - __shfl_xor_sync(0xffffffffu, u, 2);
            // z2 = (T0+T2)-(T1+T3): xor2 add, xor1 sub
            float v = T + __shfl_xor_sync(0xffffffffu, T, 2);
            zq[ms][2] = v - __shfl_xor_sync(0xffffffffu, v, 1);
        }
    }

    if (t == 0) {
        int base = blockIdx.x * TPB + wid * 32;
#pragma unroll
        for (int ms = 0; ms < 4; ms++) {
            int pg = base + g + 8 * ms;
            if (pg < NLOC)
                reinterpret_cast<float4*>(out)[pg] =
                    make_float4(zq[ms][0], zq[ms][1], zq[ms][2], zq[ms][3]);
        }
    }
}

extern "C" void kernel_launch(void* const* d_in, const int* in_sizes, int n_in,
                              void* d_out, int out_size) {
    const float* x = (const float*)d_in[0];   // [32,3,128,128] float32
    const float* w = (const float*)d_in[1];   // [4,4] float32
    float* out = (float*)d_out;               // [32,4,127,127] float32

    int blocks = (NLOC + TPB - 1) / TPB;
    rqcnn_mma<<<blocks, TPB>>>(x, w, out);
}